// round 12
// baseline (speedup 1.0000x reference)
#include <cuda_runtime.h>

// 4-qubit depth-2 variational circuit, B=2^20 samples. ONE persistent kernel.
//
// Each block computes the batch-independent tensor T_w[i0,i1,i2,i3] (81
// entries, packed as ulonglong2 wire-pairs) via amplitude-parallel gate
// evolution (256 threads, ~1.5k cycles), then grid-strides over sample tiles:
// 2 samples/thread, wire-pair f32x2 lanes, factored Horner contraction
//   z_w = sum_{i0} r0[i0] sum_{i1} r1[i1] sum_{i2} r2[i2] sum_{i3} r3[i3] T,
// r_q = (1, cos(x_q pi), sin(x_q pi)).
// __launch_bounds__(256, 3) caps regs at 84 so 3 blocks/SM stay resident
// (R11's unbounded build ballooned to 255 regs -> occ 12% -> regression).

#define PACKX2(d, lo, hi) \
    asm("mov.b64 %0, {%1, %2};" : "=l"(d) : "f"(lo), "f"(hi))
#define FMAX2(d, a, b, c) \
    asm("fma.rn.f32x2 %0, %1, %2, %3;" : "=l"(d) : "l"(a), "l"(b), "l"(c))

__global__ void __launch_bounds__(256, 3) qc_kernel(
    const float4* __restrict__ x, const float* __restrict__ w,
    ulonglong2* __restrict__ out, int h /* B/2 */, int ntiles) {
    __shared__ float bufR[16][16], bufI[16][16];  // [state s][column j]
    __shared__ float sA[4][16][16];
    __shared__ float2 sTrig[16];
    __shared__ ulonglong2 Ts[81];  // .x=(T_w0,T_w1) .y=(T_w2,T_w3)
    const int tid = threadIdx.x;

    // ================= per-block prep (amplitude-parallel) =================
    if (tid < 16) {
        float c, s;
        __sincosf(0.5f * w[tid], &s, &c);
        sTrig[tid] = make_float2(c, s);
    }
    const int j = tid & 15;
    const int st = tid >> 4;
    float ar = (st == j) ? 1.0f : 0.0f;
    float ai = 0.0f;
    __syncthreads();

#pragma unroll 1
    for (int d = 0; d < 2; ++d) {
        // composite CNOT ring permutation
        bufR[st][j] = ar; bufI[st][j] = ai;
        __syncthreads();
        {
            int src = st;
            if (src & 1) src ^= 8;
            if (src & 2) src ^= 1;
            if (src & 4) src ^= 2;
            if (src & 8) src ^= 4;
            ar = bufR[src][j]; ai = bufI[src][j];
        }
        __syncthreads();
#pragma unroll 1
        for (int q = 0; q < 4; ++q) {
            const int m = 8 >> q;
            float2 ty = sTrig[d * 8 + q * 2 + 0];
            float2 tz = sTrig[d * 8 + q * 2 + 1];
            bufR[st][j] = ar; bufI[st][j] = ai;
            __syncthreads();
            {
                float pr = bufR[st ^ m][j], pi = bufI[st ^ m][j];
                float cy = ty.x, sy = ty.y, cp = tz.x, sp = tz.y;
                float nr, ni;
                if (st & m) { nr = cy * ar + sy * pr;  ni = cy * ai + sy * pi; }
                else        { nr = cy * ar - sy * pr;  ni = cy * ai - sy * pi; }
                if (st & m) { ar = nr * cp - ni * sp;  ai = ni * cp + nr * sp; }
                else        { ar = nr * cp + ni * sp;  ai = ni * cp - nr * sp; }
            }
            __syncthreads();
        }
    }
    bufR[st][j] = ar; bufI[st][j] = ai;
    __syncthreads();

    // A_w[jj][jp] = sum_s sign_w(s)*(Ur[s][jj]Ur[s][jp]+Ui[s][jj]Ui[s][jp])
#pragma unroll 1
    for (int e = tid; e < 1024; e += 256) {
        int wq = e >> 8;
        int jj = (e >> 4) & 15;
        int jp = e & 15;
        int mask = 8 >> wq;
        float acc = 0.f;
#pragma unroll
        for (int ss = 0; ss < 16; ++ss) {
            float v = bufR[ss][jj] * bufR[ss][jp] + bufI[ss][jj] * bufI[ss][jp];
            acc += (ss & mask) ? -v : v;
        }
        sA[wq][jj][jp] = acc;
    }
    __syncthreads();

    // sparse basis change A -> T (16 nonzero (j,jp) pairs per (k,l))
    if (tid < 81) {
        int k = tid / 9, l = tid % 9;
        int i0 = k / 3, i1 = k % 3, i2 = l / 3, i3 = l % 3;
        int x0 = (i0 == 2), x1 = (i1 == 2), x2 = (i2 == 2), x3 = (i3 == 2);
        int n0 = (i0 == 1), n1 = (i1 == 1), n2 = (i2 == 1), n3 = (i3 == 1);
        float t4[4] = {0.f, 0.f, 0.f, 0.f};
#pragma unroll 1
        for (int c = 0; c < 16; ++c) {
            int o0 = (c >> 3) & 1, o1 = (c >> 2) & 1, o2 = (c >> 1) & 1, o3 = c & 1;
            int jj = (o0 << 3) | (o1 << 2) | (o2 << 1) | o3;
            int jp = ((o0 ^ x0) << 3) | ((o1 ^ x1) << 2) | ((o2 ^ x2) << 1) | (o3 ^ x3);
            int neg = (n0 & o0) ^ (n1 & o1) ^ (n2 & o2) ^ (n3 & o3);
            float sgn = neg ? -1.0f : 1.0f;
#pragma unroll
            for (int wq = 0; wq < 4; ++wq) t4[wq] += sgn * sA[wq][jj][jp];
        }
        const float inv16 = 1.0f / 16.0f;
        unsigned long long lo, hi;
        PACKX2(lo, t4[0] * inv16, t4[1] * inv16);
        PACKX2(hi, t4[2] * inv16, t4[3] * inv16);
        ulonglong2 p; p.x = lo; p.y = hi;
        Ts[tid] = p;
    }
    __syncthreads();

    // ================= persistent main loop: grid-stride tiles =================
    const float PI_F = 3.14159265358979323846f;
    for (int tile = blockIdx.x; tile < ntiles; tile += gridDim.x) {
        int t = tile * 256 + tid;
        if (t >= h) continue;

        float4 xa = x[t];
        float4 xb = x[t + h];

        float Cf[2][4], Sf[2][4];
        __sincosf(xa.x * PI_F, &Sf[0][0], &Cf[0][0]);
        __sincosf(xa.y * PI_F, &Sf[0][1], &Cf[0][1]);
        __sincosf(xa.z * PI_F, &Sf[0][2], &Cf[0][2]);
        __sincosf(xa.w * PI_F, &Sf[0][3], &Cf[0][3]);
        __sincosf(xb.x * PI_F, &Sf[1][0], &Cf[1][0]);
        __sincosf(xb.y * PI_F, &Sf[1][1], &Cf[1][1]);
        __sincosf(xb.z * PI_F, &Sf[1][2], &Cf[1][2]);
        __sincosf(xb.w * PI_F, &Sf[1][3], &Cf[1][3]);

        unsigned long long CA[4], SA[4], CB[4], SB[4];
#pragma unroll
        for (int qb = 0; qb < 4; ++qb) {
            PACKX2(CA[qb], Cf[0][qb], Cf[0][qb]);
            PACKX2(SA[qb], Sf[0][qb], Sf[0][qb]);
            PACKX2(CB[qb], Cf[1][qb], Cf[1][qb]);
            PACKX2(SB[qb], Sf[1][qb], Sf[1][qb]);
        }

        unsigned long long zA0, zA1, zB0, zB1;

#pragma unroll
        for (int i0 = 0; i0 < 3; ++i0) {
            unsigned long long tA0, tA1, tB0, tB1;
#pragma unroll
            for (int i1 = 0; i1 < 3; ++i1) {
                const int base = (i0 * 3 + i1) * 9;
                unsigned long long uA0, uA1, uB0, uB1;
#pragma unroll
                for (int i2 = 0; i2 < 3; ++i2) {
                    ulonglong2 Ta = Ts[base + i2 * 3 + 0];
                    ulonglong2 Tb = Ts[base + i2 * 3 + 1];
                    ulonglong2 Tc = Ts[base + i2 * 3 + 2];
                    unsigned long long vA0, vA1, vB0, vB1;
                    FMAX2(vA0, CA[3], Tb.x, Ta.x);
                    FMAX2(vA1, CA[3], Tb.y, Ta.y);
                    FMAX2(vB0, CB[3], Tb.x, Ta.x);
                    FMAX2(vB1, CB[3], Tb.y, Ta.y);
                    FMAX2(vA0, SA[3], Tc.x, vA0);
                    FMAX2(vA1, SA[3], Tc.y, vA1);
                    FMAX2(vB0, SB[3], Tc.x, vB0);
                    FMAX2(vB1, SB[3], Tc.y, vB1);
                    if (i2 == 0) { uA0 = vA0; uA1 = vA1; uB0 = vB0; uB1 = vB1; }
                    else if (i2 == 1) {
                        FMAX2(uA0, CA[2], vA0, uA0);
                        FMAX2(uA1, CA[2], vA1, uA1);
                        FMAX2(uB0, CB[2], vB0, uB0);
                        FMAX2(uB1, CB[2], vB1, uB1);
                    } else {
                        FMAX2(uA0, SA[2], vA0, uA0);
                        FMAX2(uA1, SA[2], vA1, uA1);
                        FMAX2(uB0, SB[2], vB0, uB0);
                        FMAX2(uB1, SB[2], vB1, uB1);
                    }
                }
                if (i1 == 0) { tA0 = uA0; tA1 = uA1; tB0 = uB0; tB1 = uB1; }
                else if (i1 == 1) {
                    FMAX2(tA0, CA[1], uA0, tA0);
                    FMAX2(tA1, CA[1], uA1, tA1);
                    FMAX2(tB0, CB[1], uB0, tB0);
                    FMAX2(tB1, CB[1], uB1, tB1);
                } else {
                    FMAX2(tA0, SA[1], uA0, tA0);
                    FMAX2(tA1, SA[1], uA1, tA1);
                    FMAX2(tB0, SB[1], uB0, tB0);
                    FMAX2(tB1, SB[1], uB1, tB1);
                }
            }
            if (i0 == 0) { zA0 = tA0; zA1 = tA1; zB0 = tB0; zB1 = tB1; }
            else if (i0 == 1) {
                FMAX2(zA0, CA[0], tA0, zA0);
                FMAX2(zA1, CA[0], tA1, zA1);
                FMAX2(zB0, CB[0], tB0, zB0);
                FMAX2(zB1, CB[0], tB1, zB1);
            } else {
                FMAX2(zA0, SA[0], tA0, zA0);
                FMAX2(zA1, SA[0], tA1, zA1);
                FMAX2(zB0, SB[0], tB0, zB0);
                FMAX2(zB1, SB[0], tB1, zB1);
            }
        }

        ulonglong2 oa; oa.x = zA0; oa.y = zA1;
        ulonglong2 ob; ob.x = zB0; ob.y = zB1;
        out[t]     = oa;
        out[t + h] = ob;
    }
}

extern "C" void kernel_launch(void* const* d_in, const int* in_sizes, int n_in,
                              void* d_out, int out_size) {
    const float* x = (const float*)d_in[0];       // [B,4]
    const float* w = (const float*)d_in[1];       // [2,4,2]
    int B = in_sizes[0] / 4;
    int h = B / 2;
    int ntiles = (h + 255) / 256;

    int sms = 148;
    cudaDeviceGetAttribute(&sms, cudaDevAttrMultiProcessorCount, 0);
    int blocks = 3 * sms;                 // 3 concurrent blocks/SM (regs capped)
    if (blocks > ntiles) blocks = ntiles;

    qc_kernel<<<blocks, 256>>>((const float4*)x, w, (ulonglong2*)d_out, h, ntiles);
}

// round 13
// speedup vs baseline: 2.5413x; 2.5413x over previous
#include <cuda_runtime.h>
#include <cuda_fp16.h>

// 4-qubit depth-2 variational circuit, B=2^20 samples. Two kernels.
//
// Split: z_w = cos(x_w*pi)  [exact fp32, the Z-identity part of A_w]
//             + sum_{k,l} T'_w[k,l] * r01[k] * r23[l]   [fp16 correction]
// where T' = T minus the unit identity entries (kl=27/9/3/1 per wire).
// Weights are O(0.01) => T' entries O(0.02) => fp16 evaluation contributes
// ~1e-4 absolute error on z in [-1,1] — inside the 1e-3 budget.
// HFMA2 rt_SMSP=2 (vs FMAX2 rt=4) halves the arithmetic floor.
// main: 2 samples/thread, wire-pair half2 lanes, factored Horner contraction.

__device__ uint2 g_T2h[81];  // .x = half2(T'_w0,T'_w1), .y = half2(T'_w2,T'_w3)

__device__ __forceinline__ __half2 u2h(unsigned v) {
    return *reinterpret_cast<__half2*>(&v);
}
__device__ __forceinline__ unsigned h2u(__half2 h) {
    return *reinterpret_cast<unsigned*>(&h);
}

// ---------------- prep: amplitude-parallel ----------------
__global__ void __launch_bounds__(384) qc_prep_kernel(const float* __restrict__ w) {
    __shared__ float bufR[16][16], bufI[16][16];  // [state s][column j]
    __shared__ float sA[4][16][16];
    __shared__ float2 sTrig[16];
    int tid = threadIdx.x;

    if (tid < 16) {
        float c, s;
        __sincosf(0.5f * w[tid], &s, &c);
        sTrig[tid] = make_float2(c, s);
    }
    const int j = tid & 15;
    const int st = tid >> 4;
    float ar = (st == j) ? 1.0f : 0.0f;
    float ai = 0.0f;
    __syncthreads();

#pragma unroll
    for (int d = 0; d < 2; ++d) {
        if (tid < 256) { bufR[st][j] = ar; bufI[st][j] = ai; }
        __syncthreads();
        if (tid < 256) {
            int src = st;
            if (src & 1) src ^= 8;
            if (src & 2) src ^= 1;
            if (src & 4) src ^= 2;
            if (src & 8) src ^= 4;
            ar = bufR[src][j]; ai = bufI[src][j];
        }
        __syncthreads();
#pragma unroll
        for (int q = 0; q < 4; ++q) {
            const int m = 8 >> q;
            float2 ty = sTrig[d * 8 + q * 2 + 0];
            float2 tz = sTrig[d * 8 + q * 2 + 1];
            if (tid < 256) { bufR[st][j] = ar; bufI[st][j] = ai; }
            __syncthreads();
            if (tid < 256) {
                float pr = bufR[st ^ m][j], pi = bufI[st ^ m][j];
                float cy = ty.x, sy = ty.y, cp = tz.x, sp = tz.y;
                float nr, ni;
                if (st & m) { nr = cy * ar + sy * pr;  ni = cy * ai + sy * pi; }
                else        { nr = cy * ar - sy * pr;  ni = cy * ai - sy * pi; }
                if (st & m) { ar = nr * cp - ni * sp;  ai = ni * cp + nr * sp; }
                else        { ar = nr * cp + ni * sp;  ai = ni * cp - nr * sp; }
            }
            __syncthreads();
        }
    }
    if (tid < 256) { bufR[st][j] = ar; bufI[st][j] = ai; }
    __syncthreads();

    for (int e = tid; e < 1024; e += 384) {
        int wq = e >> 8;
        int jj = (e >> 4) & 15;
        int jp = e & 15;
        int mask = 8 >> wq;
        float acc = 0.f;
#pragma unroll
        for (int ss = 0; ss < 16; ++ss) {
            float v = bufR[ss][jj] * bufR[ss][jp] + bufI[ss][jj] * bufI[ss][jp];
            acc += (ss & mask) ? -v : v;
        }
        sA[wq][jj][jp] = acc;
    }
    __syncthreads();

    // sparse basis change A -> T, then subtract the identity (pure-Z) entries
    // and convert to half2 wire-pairs.
    if (tid < 81) {
        int k = tid / 9, l = tid % 9;
        int i0 = k / 3, i1 = k % 3, i2 = l / 3, i3 = l % 3;
        int x0 = (i0 == 2), x1 = (i1 == 2), x2 = (i2 == 2), x3 = (i3 == 2);
        int n0 = (i0 == 1), n1 = (i1 == 1), n2 = (i2 == 1), n3 = (i3 == 1);
        float t4[4] = {0.f, 0.f, 0.f, 0.f};
#pragma unroll
        for (int c = 0; c < 16; ++c) {
            int o0 = (c >> 3) & 1, o1 = (c >> 2) & 1, o2 = (c >> 1) & 1, o3 = c & 1;
            int jj = (o0 << 3) | (o1 << 2) | (o2 << 1) | o3;
            int jp = ((o0 ^ x0) << 3) | ((o1 ^ x1) << 2) | ((o2 ^ x2) << 1) | (o3 ^ x3);
            int neg = (n0 & o0) ^ (n1 & o1) ^ (n2 & o2) ^ (n3 & o3);
            float sgn = neg ? -1.0f : 1.0f;
#pragma unroll
            for (int wq = 0; wq < 4; ++wq) t4[wq] += sgn * sA[wq][jj][jp];
        }
        const float inv16 = 1.0f / 16.0f;
        // identity entries: z_w's pure-Z term is coefficient 1 at
        // kl = 27 (w0), 9 (w1), 3 (w2), 1 (w3).
        float f0 = t4[0] * inv16 - ((tid == 27) ? 1.0f : 0.0f);
        float f1 = t4[1] * inv16 - ((tid == 9)  ? 1.0f : 0.0f);
        float f2 = t4[2] * inv16 - ((tid == 3)  ? 1.0f : 0.0f);
        float f3 = t4[3] * inv16 - ((tid == 1)  ? 1.0f : 0.0f);
        __half2 h01 = make_half2(__float2half_rn(f0), __float2half_rn(f1));
        __half2 h23 = make_half2(__float2half_rn(f2), __float2half_rn(f3));
        uint2 p; p.x = h2u(h01); p.y = h2u(h23);
        g_T2h[tid] = p;
    }
}

// ---------------- main: fp16 correction + fp32 cos base ----------------
__global__ void __launch_bounds__(256) qc_main_kernel(
    const float4* __restrict__ x, float4* __restrict__ out, int h /* B/2 */) {
    __shared__ uint2 Ts[81];
    int tid = threadIdx.x;
    if (tid < 81) Ts[tid] = g_T2h[tid];
    __syncthreads();

    int t = blockIdx.x * 256 + tid;
    if (t >= h) return;

    const float PI_F = 3.14159265358979323846f;
    float4 xa = x[t];
    float4 xb = x[t + h];

    float Cf[2][4], Sf[2][4];
    __sincosf(xa.x * PI_F, &Sf[0][0], &Cf[0][0]);
    __sincosf(xa.y * PI_F, &Sf[0][1], &Cf[0][1]);
    __sincosf(xa.z * PI_F, &Sf[0][2], &Cf[0][2]);
    __sincosf(xa.w * PI_F, &Sf[0][3], &Cf[0][3]);
    __sincosf(xb.x * PI_F, &Sf[1][0], &Cf[1][0]);
    __sincosf(xb.y * PI_F, &Sf[1][1], &Cf[1][1]);
    __sincosf(xb.z * PI_F, &Sf[1][2], &Cf[1][2]);
    __sincosf(xb.w * PI_F, &Sf[1][3], &Cf[1][3]);

    // duplicated half2 factors per sample per qubit
    __half2 CA[4], SA[4], CB[4], SB[4];
#pragma unroll
    for (int qb = 0; qb < 4; ++qb) {
        CA[qb] = __float2half2_rn(Cf[0][qb]);
        SA[qb] = __float2half2_rn(Sf[0][qb]);
        CB[qb] = __float2half2_rn(Cf[1][qb]);
        SB[qb] = __float2half2_rn(Sf[1][qb]);
    }

    // accumulators: [sample][wire-pair]; pair0 = (w0,w1), pair1 = (w2,w3)
    __half2 zA0, zA1, zB0, zB1;

#pragma unroll
    for (int i0 = 0; i0 < 3; ++i0) {
        __half2 tA0, tA1, tB0, tB1;
#pragma unroll
        for (int i1 = 0; i1 < 3; ++i1) {
            const int base = (i0 * 3 + i1) * 9;
            __half2 uA0, uA1, uB0, uB1;
#pragma unroll
            for (int i2 = 0; i2 < 3; ++i2) {
                uint2 a = Ts[base + i2 * 3 + 0];
                uint2 b = Ts[base + i2 * 3 + 1];
                uint2 c = Ts[base + i2 * 3 + 2];
                __half2 Ta0 = u2h(a.x), Ta1 = u2h(a.y);
                __half2 Tb0 = u2h(b.x), Tb1 = u2h(b.y);
                __half2 Tc0 = u2h(c.x), Tc1 = u2h(c.y);
                // v = Ta + C3*Tb + S3*Tc
                __half2 vA0 = __hfma2(CA[3], Tb0, Ta0);
                __half2 vA1 = __hfma2(CA[3], Tb1, Ta1);
                __half2 vB0 = __hfma2(CB[3], Tb0, Ta0);
                __half2 vB1 = __hfma2(CB[3], Tb1, Ta1);
                vA0 = __hfma2(SA[3], Tc0, vA0);
                vA1 = __hfma2(SA[3], Tc1, vA1);
                vB0 = __hfma2(SB[3], Tc0, vB0);
                vB1 = __hfma2(SB[3], Tc1, vB1);
                if (i2 == 0) { uA0 = vA0; uA1 = vA1; uB0 = vB0; uB1 = vB1; }
                else if (i2 == 1) {
                    uA0 = __hfma2(CA[2], vA0, uA0);
                    uA1 = __hfma2(CA[2], vA1, uA1);
                    uB0 = __hfma2(CB[2], vB0, uB0);
                    uB1 = __hfma2(CB[2], vB1, uB1);
                } else {
                    uA0 = __hfma2(SA[2], vA0, uA0);
                    uA1 = __hfma2(SA[2], vA1, uA1);
                    uB0 = __hfma2(SB[2], vB0, uB0);
                    uB1 = __hfma2(SB[2], vB1, uB1);
                }
            }
            if (i1 == 0) { tA0 = uA0; tA1 = uA1; tB0 = uB0; tB1 = uB1; }
            else if (i1 == 1) {
                tA0 = __hfma2(CA[1], uA0, tA0);
                tA1 = __hfma2(CA[1], uA1, tA1);
                tB0 = __hfma2(CB[1], uB0, tB0);
                tB1 = __hfma2(CB[1], uB1, tB1);
            } else {
                tA0 = __hfma2(SA[1], uA0, tA0);
                tA1 = __hfma2(SA[1], uA1, tA1);
                tB0 = __hfma2(SB[1], uB0, tB0);
                tB1 = __hfma2(SB[1], uB1, tB1);
            }
        }
        if (i0 == 0) { zA0 = tA0; zA1 = tA1; zB0 = tB0; zB1 = tB1; }
        else if (i0 == 1) {
            zA0 = __hfma2(CA[0], tA0, zA0);
            zA1 = __hfma2(CA[0], tA1, zA1);
            zB0 = __hfma2(CB[0], tB0, zB0);
            zB1 = __hfma2(CB[0], tB1, zB1);
        } else {
            zA0 = __hfma2(SA[0], tA0, zA0);
            zA1 = __hfma2(SA[0], tA1, zA1);
            zB0 = __hfma2(SB[0], tB0, zB0);
            zB1 = __hfma2(SB[0], tB1, zB1);
        }
    }

    // z_w = cos(x_w*pi) + fp16 correction
    out[t] = make_float4(Cf[0][0] + __low2float(zA0),
                         Cf[0][1] + __high2float(zA0),
                         Cf[0][2] + __low2float(zA1),
                         Cf[0][3] + __high2float(zA1));
    out[t + h] = make_float4(Cf[1][0] + __low2float(zB0),
                             Cf[1][1] + __high2float(zB0),
                             Cf[1][2] + __low2float(zB1),
                             Cf[1][3] + __high2float(zB1));
}

extern "C" void kernel_launch(void* const* d_in, const int* in_sizes, int n_in,
                              void* d_out, int out_size) {
    const float* x = (const float*)d_in[0];       // [B,4]
    const float* w = (const float*)d_in[1];       // [2,4,2]
    float* out = (float*)d_out;                   // [B,4]
    int B = in_sizes[0] / 4;
    int h = B / 2;

    qc_prep_kernel<<<1, 384>>>(w);
    int blocks = (h + 255) / 256;
    qc_main_kernel<<<blocks, 256>>>((const float4*)x, (float4*)out, h);
}